// round 16
// baseline (speedup 1.0000x reference)
#include <cuda_runtime.h>
#include <cuda.h>

#define K     3
#define K2    9
#define PAD   1
#define Bn    2
#define Hn    352
#define Wn    1216
#define HW    (Hn * Wn)

// Dynamic smem layout (bytes): [0,8) mbarrier, [128, +18432) weight tile
// [9][8][64] f32, [18560, +36864) offset tile [18][8][64] f32.
#define SMEM_W_OFF   128
#define SMEM_O_OFF   (128 + 18432)
#define SMEM_TOTAL   (128 + 18432 + 36864)   // 55424 B
#define TMA_BYTES    (18432 + 36864)

__device__ __forceinline__ uint32_t smem_u32(const void* p) {
    uint32_t a;
    asm("{ .reg .u64 t; cvta.to.shared.u64 t, %1; cvt.u32.u64 %0, t; }"
        : "=r"(a) : "l"(p));
    return a;
}

__device__ __forceinline__ float bilinear_safe(const float* __restrict__ img,
                                               float py, float px) {
    float y0f = floorf(py);
    float x0f = floorf(px);
    float ly  = py - y0f;
    float lx  = px - x0f;
    int y0 = (int)y0f;
    int x0 = (int)x0f;
    int y1 = y0 + 1;
    int x1 = x0 + 1;

    bool yv0 = (unsigned)y0 < Hn;
    bool yv1 = (unsigned)y1 < Hn;
    bool xv0 = (unsigned)x0 < Wn;
    bool xv1 = (unsigned)x1 < Wn;

    float v00 = 0.f, v01 = 0.f, v10 = 0.f, v11 = 0.f;
    int base0 = y0 * Wn;
    int base1 = base0 + Wn;
    if (yv0 & xv0) v00 = __ldg(img + base0 + x0);
    if (yv0 & xv1) v01 = __ldg(img + base0 + x1);
    if (yv1 & xv0) v10 = __ldg(img + base1 + x0);
    if (yv1 & xv1) v11 = __ldg(img + base1 + x1);

    float omly = 1.f - ly;
    float omlx = 1.f - lx;
    float top = fmaf(omlx, v00, lx * v01);
    float bot = fmaf(omlx, v10, lx * v11);
    return fmaf(omly, top, ly * bot);
}

// ---------------- TMA kernel: streaming loads via bulk tensor copy ----------
__global__ __launch_bounds__(256, 3)
void postproc_deconv_tma(const __grid_constant__ CUtensorMap tmap_w,
                         const __grid_constant__ CUtensorMap tmap_o,
                         const float* __restrict__ depth,
                         const float* __restrict__ wker,
                         const float* __restrict__ bias,
                         float* __restrict__ out) {
    extern __shared__ __align__(128) char smem[];
    uint32_t sb   = smem_u32(smem);
    uint32_t mbar = sb;
    const float* sw = (const float*)(smem + SMEM_W_OFF);
    const float* so = (const float*)(smem + SMEM_O_OFF);

    int tx = threadIdx.x;              // 0..31
    int ty = threadIdx.y;              // 0..7
    int tid = ty * 32 + tx;
    int bx0 = blockIdx.x * 64;
    int by0 = blockIdx.y * 8;
    int b   = blockIdx.z;

    if (tid == 0) {
        asm volatile("mbarrier.init.shared.b64 [%0], %1;" :: "r"(mbar), "r"(1) : "memory");
    }
    __syncthreads();

    if (tid == 0) {
        asm volatile("mbarrier.arrive.expect_tx.shared.b64 _, [%0], %1;"
                     :: "r"(mbar), "r"((uint32_t)TMA_BYTES) : "memory");
        asm volatile("cp.async.bulk.tensor.3d.shared::cta.global.tile.mbarrier::complete_tx::bytes "
                     "[%0], [%1, {%2, %3, %4}], [%5];"
                     :: "r"(sb + SMEM_W_OFF), "l"(&tmap_w),
                        "r"(bx0), "r"(by0), "r"(b * K2), "r"(mbar) : "memory");
        asm volatile("cp.async.bulk.tensor.3d.shared::cta.global.tile.mbarrier::complete_tx::bytes "
                     "[%0], [%1, {%2, %3, %4}], [%5];"
                     :: "r"(sb + SMEM_O_OFF), "l"(&tmap_o),
                        "r"(bx0), "r"(by0), "r"(b * 2 * K2), "r"(mbar) : "memory");
    }

    // Overlap TMA with the (independent) streamed depth read + uniforms.
    int x0  = bx0 + tx * 2;
    int y   = by0 + ty;
    int pix = y * Wn + x0;
    const float* dplane = depth + b * HW;
    float2 d2 = __ldg((const float2*)(dplane + pix));
    float bb  = __ldg(bias);

    // Wait for both TMA loads (kernel runs once -> parity 0).
    {
        uint32_t done;
        asm volatile(
            "{\n\t"
            ".reg .pred p;\n\t"
            "mbarrier.try_wait.parity.acquire.cta.shared::cta.b64 p, [%1], %2;\n\t"
            "selp.b32 %0, 1, 0, p;\n\t"
            "}"
            : "=r"(done) : "r"(mbar), "r"(0) : "memory");
        if (!done) {
            asm volatile(
                "{\n\t"
                ".reg .pred P1;\n\t"
                "WL_%=:\n\t"
                "mbarrier.try_wait.parity.acquire.cta.shared::cta.b64 P1, [%0], %1, 0x989680;\n\t"
                "@P1 bra.uni WD_%=;\n\t"
                "bra.uni WL_%=;\n\t"
                "WD_%=:\n\t"
                "}"
                :: "r"(mbar), "r"(0) : "memory");
        }
    }

    // Fused accumulators: out_j = d_j + A_j - (wsum_j/9)*S_j + bias
    float A0 = 0.f, A1 = 0.f, S0 = 0.f, S1 = 0.f, ws0 = 0.f, ws1 = 0.f;

    int lane2 = ty * 64 + tx * 2;          // [row][col] within 8x64 tile

    #pragma unroll
    for (int k = 0; k < K2; k++) {
        int kh = k / K;
        int kw = k % K;
        float2 wk2 = *(const float2*)(sw + k * 512 + lane2);
        float2 dy2 = *(const float2*)(so + (2 * k)     * 512 + lane2);
        float2 dx2 = *(const float2*)(so + (2 * k + 1) * 512 + lane2);
        float wc = __ldg(wker + k);        // uniform broadcast, L1-hit

        float py_base = (float)(y - PAD + kh);
        float px_base = (float)(x0 - PAD + kw);

        float s0 = bilinear_safe(dplane, py_base + dy2.x, px_base + dx2.x);
        float s1 = bilinear_safe(dplane, py_base + dy2.y, px_base + 1.f + dx2.y);

        float t0 = wc * s0;
        float t1 = wc * s1;
        A0 = fmaf(t0, wk2.x, A0);
        A1 = fmaf(t1, wk2.y, A1);
        S0 += t0;
        S1 += t1;
        ws0 += wk2.x;
        ws1 += wk2.y;
    }

    const float inv9 = 1.0f / 9.0f;
    float2 o2;
    o2.x = d2.x + A0 - (ws0 * inv9) * S0 + bb;
    o2.y = d2.y + A1 - (ws1 * inv9) * S1 + bb;
    *(float2*)(out + b * HW + pix) = o2;
}

// ---------------- Fallback: proven R12 kernel (25.5 us) ---------------------
__global__ __launch_bounds__(256, 4)
void postproc_deconv_ldg(const float* __restrict__ depth,
                         const float* __restrict__ weight,
                         const float* __restrict__ offset,
                         const float* __restrict__ wker,
                         const float* __restrict__ bias,
                         float* __restrict__ out) {
    int x0 = blockIdx.x * 64 + threadIdx.x * 2;
    int y  = blockIdx.y * 8  + threadIdx.y;
    int b  = blockIdx.z;

    int pix = y * Wn + x0;
    const float* dplane = depth  + b * HW;
    const float* wbase  = weight + b * (K2 * HW) + pix;
    const float* obase  = offset + b * (2 * K2 * HW) + pix;

    float2 dyv[K2], dxv[K2];
    #pragma unroll
    for (int k = 0; k < K2; k++) {
        dyv[k] = __ldg((const float2*)(obase + (2 * k)     * HW));
        dxv[k] = __ldg((const float2*)(obase + (2 * k + 1) * HW));
    }
    float2 d2 = __ldg((const float2*)(dplane + pix));

    float A0 = 0.f, A1 = 0.f, S0 = 0.f, S1 = 0.f, ws0 = 0.f, ws1 = 0.f;

    #pragma unroll
    for (int k = 0; k < K2; k++) {
        int kh = k / K;
        int kw = k % K;
        float2 wk2 = __ldg((const float2*)(wbase + k * HW));
        float wc = __ldg(wker + k);

        float py_base = (float)(y - PAD + kh);
        float px_base = (float)(x0 - PAD + kw);

        float s0 = bilinear_safe(dplane, py_base + dyv[k].x, px_base + dxv[k].x);
        float s1 = bilinear_safe(dplane, py_base + dyv[k].y, px_base + 1.f + dxv[k].y);

        float t0 = wc * s0;
        float t1 = wc * s1;
        A0 = fmaf(t0, wk2.x, A0);
        A1 = fmaf(t1, wk2.y, A1);
        S0 += t0;
        S1 += t1;
        ws0 += wk2.x;
        ws1 += wk2.y;
    }

    float bb = __ldg(bias);
    const float inv9 = 1.0f / 9.0f;

    float2 o2;
    o2.x = d2.x + A0 - (ws0 * inv9) * S0 + bb;
    o2.y = d2.y + A1 - (ws1 * inv9) * S1 + bb;
    *(float2*)(out + b * HW + pix) = o2;
}

// ---------------- Host ------------------------------------------------------
typedef CUresult (*PFN_tmapEncode)(
    CUtensorMap*, CUtensorMapDataType, cuuint32_t, void*,
    const cuuint64_t*, const cuuint64_t*, const cuuint32_t*, const cuuint32_t*,
    CUtensorMapInterleave, CUtensorMapSwizzle, CUtensorMapL2promotion,
    CUtensorMapFloatOOBfill);

extern "C" void kernel_launch(void* const* d_in, const int* in_sizes, int n_in,
                              void* d_out, int out_size) {
    const float* depth  = (const float*)d_in[0];
    const float* weight = (const float*)d_in[1];
    const float* offset = (const float*)d_in[2];
    const float* wker   = (const float*)d_in[3];
    const float* bias   = (const float*)d_in[4];
    float* out = (float*)d_out;

    dim3 block(32, 8, 1);
    dim3 grid(Wn / 64, Hn / 8, Bn);

    // Resolve driver-API tensor-map encoder via cudart (no -lcuda needed).
    PFN_tmapEncode encode = nullptr;
    cudaDriverEntryPointQueryResult qst;
    cudaGetDriverEntryPoint("cuTensorMapEncodeTiled", (void**)&encode,
                            cudaEnableDefault, &qst);

    bool ok = (encode != nullptr);
    CUtensorMap tw{}, to{};
    if (ok) {
        cuuint64_t dims_w[3]    = {Wn, Hn, (cuuint64_t)(Bn * K2)};
        cuuint64_t strides_w[2] = {(cuuint64_t)Wn * 4, (cuuint64_t)Hn * Wn * 4};
        cuuint32_t box_w[3]     = {64, 8, K2};
        cuuint32_t es[3]        = {1, 1, 1};
        ok = encode(&tw, CU_TENSOR_MAP_DATA_TYPE_FLOAT32, 3, (void*)weight,
                    dims_w, strides_w, box_w, es,
                    CU_TENSOR_MAP_INTERLEAVE_NONE, CU_TENSOR_MAP_SWIZZLE_NONE,
                    CU_TENSOR_MAP_L2_PROMOTION_L2_128B,
                    CU_TENSOR_MAP_FLOAT_OOB_FILL_NONE) == CUDA_SUCCESS;
    }
    if (ok) {
        cuuint64_t dims_o[3]    = {Wn, Hn, (cuuint64_t)(Bn * 2 * K2)};
        cuuint64_t strides_o[2] = {(cuuint64_t)Wn * 4, (cuuint64_t)Hn * Wn * 4};
        cuuint32_t box_o[3]     = {64, 8, 2 * K2};
        cuuint32_t es[3]        = {1, 1, 1};
        ok = encode(&to, CU_TENSOR_MAP_DATA_TYPE_FLOAT32, 3, (void*)offset,
                    dims_o, strides_o, box_o, es,
                    CU_TENSOR_MAP_INTERLEAVE_NONE, CU_TENSOR_MAP_SWIZZLE_NONE,
                    CU_TENSOR_MAP_L2_PROMOTION_L2_128B,
                    CU_TENSOR_MAP_FLOAT_OOB_FILL_NONE) == CUDA_SUCCESS;
    }
    if (ok) {
        ok = cudaFuncSetAttribute(postproc_deconv_tma,
                                  cudaFuncAttributeMaxDynamicSharedMemorySize,
                                  SMEM_TOTAL) == cudaSuccess;
    }

    if (ok) {
        postproc_deconv_tma<<<grid, block, SMEM_TOTAL>>>(tw, to, depth, wker, bias, out);
    } else {
        postproc_deconv_ldg<<<grid, block>>>(depth, weight, offset, wker, bias, out);
    }
}